// round 2
// baseline (speedup 1.0000x reference)
#include <cuda_runtime.h>
#include <math.h>

#define EPSF 1e-12f

static __device__ __forceinline__ float smooth_clamp(float x, float lb, float rb,
                                                     float slope_l, float slope_r) {
    float t = (x - lb) * (1.0f / (rb - lb));
    float z = 4.0f * t - 2.0f;
    float e = __expf(-z);                       // z >= -2.5 in-domain, no overflow
    float sig = __fdividef(1.0f, 1.0f + e);
    float core = lb + (rb - lb) * sig;
    float lo = fminf(x - lb, 0.0f);
    float hi = fmaxf(x - rb, 0.0f);
    return core + slope_l * lo + slope_r * hi;
}

static __device__ __forceinline__ void face_compute(
    float ax0, float ay0, float az0,
    float bx, float by, float bz,
    float cx, float cy, float cz,
    float rotz, float gsx, float gsy, float gsz,
    float col0, float col1, float col2, float logop,
    float* __restrict__ outrow)
{
    float e1x = bx - ax0, e1y = by - ay0, e1z = bz - az0;
    float e2x = cx - ax0, e2y = cy - ay0, e2z = cz - az0;

    // n = e1 x e2
    float nx = e1x * e2z;  nx = e1y * e2z - e1z * e2y;
    float ny = e1z * e2x - e1x * e2z;
    float nz = e1x * e2y - e1y * e2x;

    float nn  = nx * nx + ny * ny + nz * nz;
    float n_norm = sqrtf(nn);
    float area = 0.5f * n_norm;

    float d1  = e1x * e1x + e1y * e1y + e1z * e1z;
    float inv_e1 = rsqrtf(fmaxf(d1, 1e-24f));   // ~1/(||e1||+1e-12)
    float axx = e1x * inv_e1, axy = e1y * inv_e1, axz = e1z * inv_e1;

    float inv_n = rsqrtf(fmaxf(nn, 1e-24f));
    float azx = nx * inv_n, azy = ny * inv_n, azz = nz * inv_n;

    // ay = az x ax
    float ayx = azy * axz - azz * axy;
    float ayy = azz * axx - azx * axz;
    float ayz = azx * axy - azy * axx;

    float tx = (ax0 + bx + cx) * (1.0f / 3.0f);
    float ty = (ay0 + by + cy) * (1.0f / 3.0f);
    float tz = (az0 + bz + cz) * (1.0f / 3.0f);

    // R columns = ax, ay, az
    float m00 = axx, m01 = ayx, m02 = azx;
    float m10 = axy, m11 = ayy, m12 = azy;
    float m20 = axz, m21 = ayz, m22 = azz;

    float tr = m00 + m11 + m22;

    int idx = 0;
    float best = tr;
    if (m00 > best) { best = m00; idx = 1; }
    if (m11 > best) { best = m11; idx = 2; }
    if (m22 > best) { best = m22; idx = 3; }

    float qw, qx, qy, qz;
    if (idx == 0) {
        float t0 = fmaxf(1.0f + tr, 1e-8f);
        float s0 = 0.5f * rsqrtf(t0);
        qw = t0 * s0;
        qx = (m21 - m12) * s0;
        qy = (m02 - m20) * s0;
        qz = (m10 - m01) * s0;
    } else if (idx == 1) {
        float t1 = fmaxf(1.0f + m00 - m11 - m22, 1e-8f);
        float s1 = 0.5f * rsqrtf(t1);
        qw = (m21 - m12) * s1;
        qx = t1 * s1;
        qy = (m01 + m10) * s1;
        qz = (m02 + m20) * s1;
    } else if (idx == 2) {
        float t2 = fmaxf(1.0f - m00 + m11 - m22, 1e-8f);
        float s2 = 0.5f * rsqrtf(t2);
        qw = (m02 - m20) * s2;
        qx = (m01 + m10) * s2;
        qy = t2 * s2;
        qz = (m12 + m21) * s2;
    } else {
        float t3 = fmaxf(1.0f - m00 - m11 + m22, 1e-8f);
        float s3 = 0.5f * rsqrtf(t3);
        qw = (m10 - m01) * s3;
        qx = (m02 + m20) * s3;
        qy = (m12 + m21) * s3;
        qz = t3 * s3;
    }

    float half = rotz * 0.5f;
    float sh, ch;
    __sincosf(half, &sh, &ch);
    float wqw = qw * ch - qz * sh;
    float wqx = qx * ch + qy * sh;
    float wqy = qy * ch - qx * sh;
    float wqz = qw * sh + qz * ch;

    float sf = sqrtf(area);
    float sx = sf * smooth_clamp(__expf(gsx), 0.1f, 3.0f, 0.0f, 0.005f);
    float sy = sf * smooth_clamp(__expf(gsy), 0.1f, 3.0f, 0.0f, 0.005f);
    float sz = smooth_clamp(sf * __expf(gsz), 0.001f, 0.01f, 0.0f, 0.005f);

    float opacity = __expf(logop);

    // row byte offset = 56*i -> 8-byte aligned, float2 stores legal
    float2* o2 = reinterpret_cast<float2*>(outrow);
    o2[0] = make_float2(tx, ty);
    o2[1] = make_float2(tz, wqw);
    o2[2] = make_float2(wqx, wqy);
    o2[3] = make_float2(wqz, sx);
    o2[4] = make_float2(sy, sz);
    o2[5] = make_float2(col0, col1);
    o2[6] = make_float2(col2, opacity);
}

__global__ void __launch_bounds__(128) face_gaussian_v4(
    const float* __restrict__ va,
    const float* __restrict__ vb,
    const float* __restrict__ vc,
    const float* __restrict__ rotz,
    const float* __restrict__ gsx,
    const float* __restrict__ gsy,
    const float* __restrict__ gsz,
    const float* __restrict__ color,
    const float* __restrict__ logop,
    float* __restrict__ out,
    int F)
{
    int g  = blockIdx.x * blockDim.x + threadIdx.x;
    int i0 = g * 4;
    if (i0 >= F) return;

    if (i0 + 4 <= F) {
        const float4* va4  = reinterpret_cast<const float4*>(va);
        const float4* vb4  = reinterpret_cast<const float4*>(vb);
        const float4* vc4  = reinterpret_cast<const float4*>(vc);
        const float4* co4  = reinterpret_cast<const float4*>(color);

        float4 A0 = va4[3 * g], A1 = va4[3 * g + 1], A2 = va4[3 * g + 2];
        float4 B0 = vb4[3 * g], B1 = vb4[3 * g + 1], B2 = vb4[3 * g + 2];
        float4 C0 = vc4[3 * g], C1 = vc4[3 * g + 1], C2 = vc4[3 * g + 2];
        float4 K0 = co4[3 * g], K1 = co4[3 * g + 1], K2 = co4[3 * g + 2];
        float4 RZ = reinterpret_cast<const float4*>(rotz)[g];
        float4 SX = reinterpret_cast<const float4*>(gsx)[g];
        float4 SY = reinterpret_cast<const float4*>(gsy)[g];
        float4 SZ = reinterpret_cast<const float4*>(gsz)[g];
        float4 OP = reinterpret_cast<const float4*>(logop)[g];

        float av[12] = {A0.x, A0.y, A0.z, A0.w, A1.x, A1.y, A1.z, A1.w, A2.x, A2.y, A2.z, A2.w};
        float bv[12] = {B0.x, B0.y, B0.z, B0.w, B1.x, B1.y, B1.z, B1.w, B2.x, B2.y, B2.z, B2.w};
        float cv[12] = {C0.x, C0.y, C0.z, C0.w, C1.x, C1.y, C1.z, C1.w, C2.x, C2.y, C2.z, C2.w};
        float kv[12] = {K0.x, K0.y, K0.z, K0.w, K1.x, K1.y, K1.z, K1.w, K2.x, K2.y, K2.z, K2.w};
        float rz[4] = {RZ.x, RZ.y, RZ.z, RZ.w};
        float xs[4] = {SX.x, SX.y, SX.z, SX.w};
        float ys[4] = {SY.x, SY.y, SY.z, SY.w};
        float zs[4] = {SZ.x, SZ.y, SZ.z, SZ.w};
        float op[4] = {OP.x, OP.y, OP.z, OP.w};

        #pragma unroll
        for (int f = 0; f < 4; f++) {
            face_compute(av[3 * f], av[3 * f + 1], av[3 * f + 2],
                         bv[3 * f], bv[3 * f + 1], bv[3 * f + 2],
                         cv[3 * f], cv[3 * f + 1], cv[3 * f + 2],
                         rz[f], xs[f], ys[f], zs[f],
                         kv[3 * f], kv[3 * f + 1], kv[3 * f + 2], op[f],
                         out + (size_t)(i0 + f) * 14);
        }
    } else {
        for (int i = i0; i < F; i++) {
            int i3 = 3 * i;
            face_compute(va[i3], va[i3 + 1], va[i3 + 2],
                         vb[i3], vb[i3 + 1], vb[i3 + 2],
                         vc[i3], vc[i3 + 1], vc[i3 + 2],
                         rotz[i], gsx[i], gsy[i], gsz[i],
                         color[i3], color[i3 + 1], color[i3 + 2], logop[i],
                         out + (size_t)i * 14);
        }
    }
}

extern "C" void kernel_launch(void* const* d_in, const int* in_sizes, int n_in,
                              void* d_out, int out_size)
{
    const float* va    = (const float*)d_in[0];
    const float* vb    = (const float*)d_in[1];
    const float* vc    = (const float*)d_in[2];
    const float* rotz  = (const float*)d_in[3];
    const float* gsx   = (const float*)d_in[4];
    const float* gsy   = (const float*)d_in[5];
    const float* gsz   = (const float*)d_in[6];
    const float* color = (const float*)d_in[7];
    const float* logop = (const float*)d_in[8];
    float* out = (float*)d_out;

    int F = in_sizes[3];                 // gp_rot_z element count
    int groups = (F + 3) / 4;
    int threads = 128;
    int blocks = (groups + threads - 1) / threads;
    face_gaussian_v4<<<blocks, threads>>>(va, vb, vc, rotz, gsx, gsy, gsz,
                                          color, logop, out, F);
}

// round 5
// speedup vs baseline: 1.5414x; 1.5414x over previous
#include <cuda_runtime.h>
#include <math.h>

#define EPSF 1e-12f

struct V3 { float x, y, z; };

static __device__ __forceinline__ V3 v3sub(V3 a, V3 b) { return {a.x - b.x, a.y - b.y, a.z - b.z}; }
static __device__ __forceinline__ V3 v3cross(V3 a, V3 b) {
    return {a.y * b.z - a.z * b.y,
            a.z * b.x - a.x * b.z,
            a.x * b.y - a.y * b.x};
}
static __device__ __forceinline__ float v3dot(V3 a, V3 b) { return a.x * b.x + a.y * b.y + a.z * b.z; }

static __device__ __forceinline__ float smooth_clamp(float x, float lb, float rb,
                                                     float slope_l, float slope_r) {
    float t = (x - lb) * (1.0f / (rb - lb));
    float z = 4.0f * t - 2.0f;
    float e = __expf(-z);
    float sig = __fdividef(1.0f, 1.0f + e);
    float core = lb + (rb - lb) * sig;
    float lo = fminf(x - lb, 0.0f);
    float hi = fmaxf(x - rb, 0.0f);
    return core + slope_l * lo + slope_r * hi;
}

__global__ void __launch_bounds__(256) face_gaussian_kernel(
    const float* __restrict__ va,
    const float* __restrict__ vb,
    const float* __restrict__ vc,
    const float* __restrict__ rotz,
    const float* __restrict__ gsx,
    const float* __restrict__ gsy,
    const float* __restrict__ gsz,
    const float* __restrict__ color,
    const float* __restrict__ logop,
    float* __restrict__ out,
    int F)
{
    int i = blockIdx.x * blockDim.x + threadIdx.x;
    if (i >= F) return;

    const int i3 = 3 * i;
    V3 a = {va[i3], va[i3 + 1], va[i3 + 2]};
    V3 b = {vb[i3], vb[i3 + 1], vb[i3 + 2]};
    V3 c = {vc[i3], vc[i3 + 1], vc[i3 + 2]};

    V3 e1 = v3sub(b, a);
    V3 e2 = v3sub(c, a);
    V3 n = v3cross(e1, e2);
    float nn = v3dot(n, n);
    float n_norm = sqrtf(nn);
    float area = 0.5f * n_norm;

    // 1/(||e1|| + eps) ~= rsqrt(max(||e1||^2, tiny)); validated rel_err ~1e-7
    float inv_e1 = rsqrtf(fmaxf(v3dot(e1, e1), 1e-24f));
    V3 ax = {e1.x * inv_e1, e1.y * inv_e1, e1.z * inv_e1};
    float inv_n = rsqrtf(fmaxf(nn, 1e-24f));
    V3 az = {n.x * inv_n, n.y * inv_n, n.z * inv_n};
    V3 ay = v3cross(az, ax);

    float tx = (a.x + b.x + c.x) * (1.0f / 3.0f);
    float ty = (a.y + b.y + c.y) * (1.0f / 3.0f);
    float tz = (a.z + b.z + c.z) * (1.0f / 3.0f);

    // R columns = ax, ay, az
    float m00 = ax.x, m01 = ay.x, m02 = az.x;
    float m10 = ax.y, m11 = ay.y, m12 = az.y;
    float m20 = ax.z, m21 = ay.z, m22 = az.z;

    float tr = m00 + m11 + m22;

    int idx = 0;
    float best = tr;
    if (m00 > best) { best = m00; idx = 1; }
    if (m11 > best) { best = m11; idx = 2; }
    if (m22 > best) { best = m22; idx = 3; }

    float qw, qx, qy, qz;
    if (idx == 0) {
        float t0 = fmaxf(1.0f + tr, 1e-8f);
        float s0 = 0.5f * rsqrtf(t0);
        qw = t0 * s0;
        qx = (m21 - m12) * s0;
        qy = (m02 - m20) * s0;
        qz = (m10 - m01) * s0;
    } else if (idx == 1) {
        float t1 = fmaxf(1.0f + m00 - m11 - m22, 1e-8f);
        float s1 = 0.5f * rsqrtf(t1);
        qw = (m21 - m12) * s1;
        qx = t1 * s1;
        qy = (m01 + m10) * s1;
        qz = (m02 + m20) * s1;
    } else if (idx == 2) {
        float t2 = fmaxf(1.0f - m00 + m11 - m22, 1e-8f);
        float s2 = 0.5f * rsqrtf(t2);
        qw = (m02 - m20) * s2;
        qx = (m01 + m10) * s2;
        qy = t2 * s2;
        qz = (m12 + m21) * s2;
    } else {
        float t3 = fmaxf(1.0f - m00 - m11 + m22, 1e-8f);
        float s3 = 0.5f * rsqrtf(t3);
        qw = (m10 - m01) * s3;
        qx = (m02 + m20) * s3;
        qy = (m12 + m21) * s3;
        qz = t3 * s3;
    }

    float half = rotz[i] * 0.5f;
    float sh, ch;
    __sincosf(half, &sh, &ch);
    float wqw = qw * ch - qz * sh;
    float wqx = qx * ch + qy * sh;
    float wqy = qy * ch - qx * sh;
    float wqz = qw * sh + qz * ch;

    float sf = sqrtf(area);
    float sx = sf * smooth_clamp(__expf(gsx[i]), 0.1f, 3.0f, 0.0f, 0.005f);
    float sy = sf * smooth_clamp(__expf(gsy[i]), 0.1f, 3.0f, 0.0f, 0.005f);
    float sz = smooth_clamp(sf * __expf(gsz[i]), 0.001f, 0.01f, 0.0f, 0.005f);

    float col0 = color[i3];
    float col1 = color[i3 + 1];
    float col2 = color[i3 + 2];
    float opacity = __expf(logop[i]);

    // Output row: 14 floats, byte offset 56*i -> 8B aligned, float2 stores legal.
    float2* o2 = reinterpret_cast<float2*>(out + (size_t)i * 14);
    o2[0] = make_float2(tx, ty);
    o2[1] = make_float2(tz, wqw);
    o2[2] = make_float2(wqx, wqy);
    o2[3] = make_float2(wqz, sx);
    o2[4] = make_float2(sy, sz);
    o2[5] = make_float2(col0, col1);
    o2[6] = make_float2(col2, opacity);
}

extern "C" void kernel_launch(void* const* d_in, const int* in_sizes, int n_in,
                              void* d_out, int out_size)
{
    const float* va    = (const float*)d_in[0];
    const float* vb    = (const float*)d_in[1];
    const float* vc    = (const float*)d_in[2];
    const float* rotz  = (const float*)d_in[3];
    const float* gsx   = (const float*)d_in[4];
    const float* gsy   = (const float*)d_in[5];
    const float* gsz   = (const float*)d_in[6];
    const float* color = (const float*)d_in[7];
    const float* logop = (const float*)d_in[8];
    float* out = (float*)d_out;

    int F = in_sizes[3];  // gp_rot_z element count
    int threads = 256;
    int blocks = (F + threads - 1) / threads;
    face_gaussian_kernel<<<blocks, threads>>>(va, vb, vc, rotz, gsx, gsy, gsz,
                                              color, logop, out, F);
}